// round 12
// baseline (speedup 1.0000x reference)
#include <cuda_runtime.h>
#include <math.h>

#define BB  16
#define NQ  256
#define NKV 256
#define DD  64
#define TILES 8
#define TK 32

__device__ float g_proj[BB * NKV * 3 * DD];

// ---------------------------------------------------------------------------
// Kernel A: proj = v_equi @ W_coord^T  (12288 rows of 64). grid=768, one
// 4-row quad per warp; v loads issued before Wt staging to overlap.
// ---------------------------------------------------------------------------
__global__ void __launch_bounds__(128) proj_kernel(const float* __restrict__ v,
                                                   const float* __restrict__ Wc) {
    __shared__ __align__(16) float Wt[64 * 66];
    __shared__ __align__(16) float vbuf[4][4][64];

    int t = threadIdx.x;
    int w = t >> 5, l = t & 31;
    int qd = blockIdx.x * 4 + w;

    float2 v0 = ((const float2*)(v + (size_t)(qd * 4 + 0) * 64))[l];
    float2 v1 = ((const float2*)(v + (size_t)(qd * 4 + 1) * 64))[l];
    float2 v2 = ((const float2*)(v + (size_t)(qd * 4 + 2) * 64))[l];
    float2 v3 = ((const float2*)(v + (size_t)(qd * 4 + 3) * 64))[l];

    for (int i = t; i < 4096; i += 128) {
        Wt[(i & 63) * 66 + (i >> 6)] = Wc[i];
    }

    vbuf[w][0][2 * l] = v0.x;  vbuf[w][0][2 * l + 1] = v0.y;
    vbuf[w][1][2 * l] = v1.x;  vbuf[w][1][2 * l + 1] = v1.y;
    vbuf[w][2][2 * l] = v2.x;  vbuf[w][2][2 * l + 1] = v2.y;
    vbuf[w][3][2 * l] = v3.x;  vbuf[w][3][2 * l + 1] = v3.y;
    __syncthreads();

    float ax[4] = {0.f, 0.f, 0.f, 0.f};
    float ay[4] = {0.f, 0.f, 0.f, 0.f};
    #pragma unroll
    for (int e4 = 0; e4 < 16; e4++) {
        float4 va[4];
        #pragma unroll
        for (int r = 0; r < 4; r++) va[r] = *(const float4*)&vbuf[w][r][e4 * 4];
        #pragma unroll
        for (int i = 0; i < 4; i++) {
            float2 wt = *(const float2*)(Wt + (e4 * 4 + i) * 66 + 2 * l);
            #pragma unroll
            for (int r = 0; r < 4; r++) {
                float fr = ((const float*)&va[r])[i];
                ax[r] = fmaf(fr, wt.x, ax[r]);
                ay[r] = fmaf(fr, wt.y, ay[r]);
            }
        }
    }
    #pragma unroll
    for (int r = 0; r < 4; r++) {
        ((float2*)(g_proj + (size_t)(qd * 4 + r) * 64))[l] = make_float2(ax[r], ay[r]);
    }
}

// ---------------------------------------------------------------------------
// Main kernel. CTA = (b, 8 q's), 8 warps/256 thr, grid 512 (R8 structure).
// k-space in 8 tiles of 32 (TK=32 halves the per-tile barrier imbalance tax
// vs TK=16: max-of-8-warps Binomial(32,.5) ~ 20 vs mean 16). Each tile's proj
// (24KB) cp.async-staged once per CTA, shared by all 8 q-warps. Inner loop:
// rotation-free depth-3/unroll-3 register pipeline (zero MOVs per k), exact
// rotating tail (<=2 per tile).
// ---------------------------------------------------------------------------
__global__ void __launch_bounds__(256, 4) attn_kernel(const float* __restrict__ msg,
                                                      const int*   __restrict__ adjm,
                                                      const float* __restrict__ Wa,
                                                      float*       __restrict__ out) {
    __shared__ __align__(16) float projT[2][TK][3][64];      // 48KB, overlaid later
    __shared__ unsigned char  klist[8][NKV + 8];
    __shared__ unsigned short jb[8][TILES + 1];

    float* WtS = &projT[0][0][0][0];          // 64*65 = 4160 floats
    float* aoS = WtS + 4160;                  // 24*64 = 1536 floats (5696 < 12288)

    int t = threadIdx.x;
    int w = t >> 5, l = t & 31;
    int b = blockIdx.x >> 5;
    int qbase = (blockIdx.x & 31) << 3;
    int q = qbase + w;

    const float2* msg2   = (const float2*)msg + (size_t)(b * NQ + q) * (NKV * 32);
    const float4* projG4 = (const float4*)g_proj + (size_t)b * (NKV * 48);
    float4* projS4 = (float4*)&projT[0][0][0][0];

#define CP16(dst_, src_)                                                        \
    asm volatile("cp.async.cg.shared.global [%0], [%1], 16;"                    \
                 :: "r"((unsigned)__cvta_generic_to_shared(dst_)), "l"(src_) : "memory")

    // stage proj tile 0 (TK*48 = 1536 float4 / 256 threads = 6 each)
    #pragma unroll
    for (int i = 0; i < 6; i++) CP16(projS4 + t + i * 256, projG4 + t + i * 256);
    asm volatile("cp.async.commit_group;" ::: "memory");

    // ---- build mask, compact klist, tile boundaries (32-aligned) ----
    const int* arow = adjm + (b * NQ + q) * NKV;
    unsigned mask[8];
    unsigned any = 0u;
    #pragma unroll
    for (int c = 0; c < 8; c++) {
        mask[c] = __ballot_sync(0xffffffffu, arow[c * 32 + l] != 0);
        any |= mask[c];
    }
    if (!any) {
        #pragma unroll
        for (int c = 0; c < 8; c++) mask[c] = 0xffffffffu;
    }
    int cnt = 0;
    #pragma unroll
    for (int c = 0; c < 8; c++) {
        unsigned m = mask[c];
        if ((m >> l) & 1u) {
            klist[w][cnt + __popc(m & ((1u << l) - 1u))] = (unsigned char)(c * 32 + l);
        }
        cnt += __popc(m);
    }
    __syncwarp();
    if (l < 8) klist[w][cnt + l] = klist[w][cnt - 1];     // pad (cnt >= 1 always)
    if (l <= TILES) {        // jb[l] = #active k < 32*l
        int s = 0;
        #pragma unroll
        for (int c = 0; c < 8; c++) {
            if (c < l) s += __popc(mask[c]);
        }
        jb[w][l] = (unsigned short)s;
    }
    __syncwarp();

    // rotation-free pipeline prologue (depth 3 == unroll 3)
    int K0 = klist[w][0], K1 = klist[w][1], K2 = klist[w][2];
    float2 M0 = msg2[K0 * 32 + l];
    float2 M1 = msg2[K1 * 32 + l];
    float2 M2 = msg2[K2 * 32 + l];

    asm volatile("cp.async.wait_group 0;" ::: "memory");
    __syncthreads();

    float2 dn = {0.f, 0.f}, w2 = {0.f, 0.f};
    float2 A0 = {0.f, 0.f}, A1 = {0.f, 0.f}, A2 = {0.f, 0.f};

#define CONSUME(m_, kc_)                                                        \
    do {                                                                        \
        const float* pb = pbase + (kc_) * 192;                                  \
        float2 p0 = *(const float2*)(pb);                                       \
        float2 p1 = *(const float2*)(pb + 64);                                  \
        float2 p2 = *(const float2*)(pb + 128);                                 \
        float e0 = __expf((m_).x);                                              \
        float e1 = __expf((m_).y);                                              \
        dn.x += e0;                    dn.y += e1;                              \
        w2.x = fmaf(e0, e0, w2.x);     w2.y = fmaf(e1, e1, w2.y);               \
        A0.x = fmaf(e0, p0.x, A0.x);   A0.y = fmaf(e1, p0.y, A0.y);             \
        A1.x = fmaf(e0, p1.x, A1.x);   A1.y = fmaf(e1, p1.y, A1.y);             \
        A2.x = fmaf(e0, p2.x, A2.x);   A2.y = fmaf(e1, p2.y, A2.y);             \
    } while (0)

#define STEP3(MS, KS, jv)                                                       \
    do {                                                                        \
        float2 mcur = MS;  int kcur = KS;                                       \
        KS = klist[w][(jv) + 3];                                                \
        MS = msg2[KS * 32 + l];                                                 \
        CONSUME(mcur, kcur);                                                    \
    } while (0)

    for (int T = 0; T < TILES; T++) {
        // stage tile T+1 into the other buffer (1 commit per tile)
        if (T + 1 < TILES) {
            const float4* src = projG4 + (T + 1) * (TK * 48);
            float4* dst = projS4 + ((T + 1) & 1) * (TK * 48);
            #pragma unroll
            for (int i = 0; i < 6; i++) CP16(dst + t + i * 256, src + t + i * 256);
        }
        asm volatile("cp.async.commit_group;" ::: "memory");

        int js = jb[w][T], je = jb[w][T + 1];
        const float* pbase = &projT[T & 1][0][0][0] + 2 * l - T * (TK * 192);
        int j = js;
        while (je - j >= 3) {              // rotation-free: regs cycle in place
            STEP3(M0, K0, j);
            STEP3(M1, K1, j + 1);
            STEP3(M2, K2, j + 2);
            j += 3;
        }
        while (j < je) {                   // exact rotating tail (<=2)
            float2 mcur = M0;  int kcur = K0;
            M0 = M1; K0 = K1; M1 = M2; K1 = K2;
            K2 = klist[w][j + 3];
            M2 = msg2[K2 * 32 + l];
            CONSUME(mcur, kcur);
            j++;
        }

        asm volatile("cp.async.wait_group 0;" ::: "memory");
        __syncthreads();
    }
#undef STEP3
#undef CONSUME
#undef CP16

    // ---- finalize: attn_out = acc * sqrt(w2) / den^2  (write into overlay) ----
    float sx = sqrtf(w2.x) / (dn.x * dn.x);
    float sy = sqrtf(w2.y) / (dn.y * dn.y);
    aoS[(w * 3 + 0) * 64 + 2 * l] = A0.x * sx;  aoS[(w * 3 + 0) * 64 + 2 * l + 1] = A0.y * sy;
    aoS[(w * 3 + 1) * 64 + 2 * l] = A1.x * sx;  aoS[(w * 3 + 1) * 64 + 2 * l + 1] = A1.y * sy;
    aoS[(w * 3 + 2) * 64 + 2 * l] = A2.x * sx;  aoS[(w * 3 + 2) * 64 + 2 * l + 1] = A2.y * sy;

    // stage Wt (transposed W_attn) into the union region
    for (int i = t; i < 4096; i += 256) {
        WtS[(i & 63) * 65 + (i >> 6)] = Wa[i];
    }
    __syncthreads();

    // ---- epilogue: out[(q,c),d] = sum_e ao[(q,c)][e] * Wa[d][e] ----
    int d = t & 63;
    int g = t >> 6;                    // 0..3 -> 6 rows each (24 rows)
    float acc[6];
    #pragma unroll
    for (int jj = 0; jj < 6; jj++) acc[jj] = 0.f;
    #pragma unroll 4
    for (int e = 0; e < 64; e++) {
        float wt = WtS[e * 65 + d];
        #pragma unroll
        for (int jj = 0; jj < 6; jj++) {
            acc[jj] = fmaf(aoS[(g + 4 * jj) * 64 + e], wt, acc[jj]);
        }
    }
    float* orow = out + ((size_t)(b * NQ + qbase) * 3) * 64;
    #pragma unroll
    for (int jj = 0; jj < 6; jj++) {
        int r = g + 4 * jj;            // r = q_local*3 + c
        orow[r * 64 + d] = acc[jj];
    }
}

extern "C" void kernel_launch(void* const* d_in, const int* in_sizes, int n_in,
                              void* d_out, int out_size) {
    const float* v_equi   = (const float*)d_in[0];
    const float* messages = (const float*)d_in[1];
    const int*   adj_mask = (const int*)d_in[2];
    const float* W_coord  = (const float*)d_in[3];
    const float* W_attn   = (const float*)d_in[4];
    float* out = (float*)d_out;

    proj_kernel<<<768, 128>>>(v_equi, W_coord);
    attn_kernel<<<BB * (NQ / 8), 256>>>(messages, adj_mask, W_attn, out);
}

// round 13
// speedup vs baseline: 1.2341x; 1.2341x over previous
#include <cuda_runtime.h>
#include <math.h>

#define BB  16
#define NQ  256
#define NKV 256
#define DD  64
#define TILES 8
#define TK 32

__device__ float g_proj[BB * NKV * 3 * DD];

// ---------------------------------------------------------------------------
// Kernel A: proj = v_equi @ W_coord^T  (12288 rows of 64). grid=768, one
// 4-row quad per warp; v loads issued before Wt staging to overlap.
// ---------------------------------------------------------------------------
__global__ void __launch_bounds__(128) proj_kernel(const float* __restrict__ v,
                                                   const float* __restrict__ Wc) {
    __shared__ __align__(16) float Wt[64 * 66];
    __shared__ __align__(16) float vbuf[4][4][64];

    int t = threadIdx.x;
    int w = t >> 5, l = t & 31;
    int qd = blockIdx.x * 4 + w;

    float2 v0 = ((const float2*)(v + (size_t)(qd * 4 + 0) * 64))[l];
    float2 v1 = ((const float2*)(v + (size_t)(qd * 4 + 1) * 64))[l];
    float2 v2 = ((const float2*)(v + (size_t)(qd * 4 + 2) * 64))[l];
    float2 v3 = ((const float2*)(v + (size_t)(qd * 4 + 3) * 64))[l];

    for (int i = t; i < 4096; i += 128) {
        Wt[(i & 63) * 66 + (i >> 6)] = Wc[i];
    }

    vbuf[w][0][2 * l] = v0.x;  vbuf[w][0][2 * l + 1] = v0.y;
    vbuf[w][1][2 * l] = v1.x;  vbuf[w][1][2 * l + 1] = v1.y;
    vbuf[w][2][2 * l] = v2.x;  vbuf[w][2][2 * l + 1] = v2.y;
    vbuf[w][3][2 * l] = v3.x;  vbuf[w][3][2 * l + 1] = v3.y;
    __syncthreads();

    float ax[4] = {0.f, 0.f, 0.f, 0.f};
    float ay[4] = {0.f, 0.f, 0.f, 0.f};
    #pragma unroll
    for (int e4 = 0; e4 < 16; e4++) {
        float4 va[4];
        #pragma unroll
        for (int r = 0; r < 4; r++) va[r] = *(const float4*)&vbuf[w][r][e4 * 4];
        #pragma unroll
        for (int i = 0; i < 4; i++) {
            float2 wt = *(const float2*)(Wt + (e4 * 4 + i) * 66 + 2 * l);
            #pragma unroll
            for (int r = 0; r < 4; r++) {
                float fr = ((const float*)&va[r])[i];
                ax[r] = fmaf(fr, wt.x, ax[r]);
                ay[r] = fmaf(fr, wt.y, ay[r]);
            }
        }
    }
    #pragma unroll
    for (int r = 0; r < 4; r++) {
        ((float2*)(g_proj + (size_t)(qd * 4 + r) * 64))[l] = make_float2(ax[r], ay[r]);
    }
}

// ---------------------------------------------------------------------------
// Main kernel. CTA = (b, 8 q's), 8 warps/256 thr, grid 512 (R8 structure).
// k-space in 8 tiles of 32 (TK=32 halves the per-tile barrier imbalance tax
// vs TK=16: max-of-8-warps Binomial(32,.5) ~ 20 vs mean 16). Each tile's proj
// (24KB) cp.async-staged once per CTA, shared by all 8 q-warps. Inner loop:
// rotation-free depth-3/unroll-3 register pipeline (zero MOVs per k), exact
// rotating tail (<=2 per tile).
// ---------------------------------------------------------------------------
__global__ void __launch_bounds__(256, 4) attn_kernel(const float* __restrict__ msg,
                                                      const int*   __restrict__ adjm,
                                                      const float* __restrict__ Wa,
                                                      float*       __restrict__ out) {
    __shared__ __align__(16) float projT[2][TK][3][64];      // 48KB, overlaid later
    __shared__ unsigned char  klist[8][NKV + 8];
    __shared__ unsigned short jb[8][TILES + 1];

    float* WtS = &projT[0][0][0][0];          // 64*65 = 4160 floats
    float* aoS = WtS + 4160;                  // 24*64 = 1536 floats (5696 < 12288)

    int t = threadIdx.x;
    int w = t >> 5, l = t & 31;
    int b = blockIdx.x >> 5;
    int qbase = (blockIdx.x & 31) << 3;
    int q = qbase + w;

    const float2* msg2   = (const float2*)msg + (size_t)(b * NQ + q) * (NKV * 32);
    const float4* projG4 = (const float4*)g_proj + (size_t)b * (NKV * 48);
    float4* projS4 = (float4*)&projT[0][0][0][0];

#define CP16(dst_, src_)                                                        \
    asm volatile("cp.async.cg.shared.global [%0], [%1], 16;"                    \
                 :: "r"((unsigned)__cvta_generic_to_shared(dst_)), "l"(src_) : "memory")

    // stage proj tile 0 (TK*48 = 1536 float4 / 256 threads = 6 each)
    #pragma unroll
    for (int i = 0; i < 6; i++) CP16(projS4 + t + i * 256, projG4 + t + i * 256);
    asm volatile("cp.async.commit_group;" ::: "memory");

    // ---- build mask, compact klist, tile boundaries (32-aligned) ----
    const int* arow = adjm + (b * NQ + q) * NKV;
    unsigned mask[8];
    unsigned any = 0u;
    #pragma unroll
    for (int c = 0; c < 8; c++) {
        mask[c] = __ballot_sync(0xffffffffu, arow[c * 32 + l] != 0);
        any |= mask[c];
    }
    if (!any) {
        #pragma unroll
        for (int c = 0; c < 8; c++) mask[c] = 0xffffffffu;
    }
    int cnt = 0;
    #pragma unroll
    for (int c = 0; c < 8; c++) {
        unsigned m = mask[c];
        if ((m >> l) & 1u) {
            klist[w][cnt + __popc(m & ((1u << l) - 1u))] = (unsigned char)(c * 32 + l);
        }
        cnt += __popc(m);
    }
    __syncwarp();
    if (l < 8) klist[w][cnt + l] = klist[w][cnt - 1];     // pad (cnt >= 1 always)
    if (l <= TILES) {        // jb[l] = #active k < 32*l
        int s = 0;
        #pragma unroll
        for (int c = 0; c < 8; c++) {
            if (c < l) s += __popc(mask[c]);
        }
        jb[w][l] = (unsigned short)s;
    }
    __syncwarp();

    // rotation-free pipeline prologue (depth 3 == unroll 3)
    int K0 = klist[w][0], K1 = klist[w][1], K2 = klist[w][2];
    float2 M0 = msg2[K0 * 32 + l];
    float2 M1 = msg2[K1 * 32 + l];
    float2 M2 = msg2[K2 * 32 + l];

    asm volatile("cp.async.wait_group 0;" ::: "memory");
    __syncthreads();

    float2 dn = {0.f, 0.f}, w2 = {0.f, 0.f};
    float2 A0 = {0.f, 0.f}, A1 = {0.f, 0.f}, A2 = {0.f, 0.f};

#define CONSUME(m_, kc_)                                                        \
    do {                                                                        \
        const float* pb = pbase + (kc_) * 192;                                  \
        float2 p0 = *(const float2*)(pb);                                       \
        float2 p1 = *(const float2*)(pb + 64);                                  \
        float2 p2 = *(const float2*)(pb + 128);                                 \
        float e0 = __expf((m_).x);                                              \
        float e1 = __expf((m_).y);                                              \
        dn.x += e0;                    dn.y += e1;                              \
        w2.x = fmaf(e0, e0, w2.x);     w2.y = fmaf(e1, e1, w2.y);               \
        A0.x = fmaf(e0, p0.x, A0.x);   A0.y = fmaf(e1, p0.y, A0.y);             \
        A1.x = fmaf(e0, p1.x, A1.x);   A1.y = fmaf(e1, p1.y, A1.y);             \
        A2.x = fmaf(e0, p2.x, A2.x);   A2.y = fmaf(e1, p2.y, A2.y);             \
    } while (0)

#define STEP3(MS, KS, jv)                                                       \
    do {                                                                        \
        float2 mcur = MS;  int kcur = KS;                                       \
        KS = klist[w][(jv) + 3];                                                \
        MS = msg2[KS * 32 + l];                                                 \
        CONSUME(mcur, kcur);                                                    \
    } while (0)

    for (int T = 0; T < TILES; T++) {
        // stage tile T+1 into the other buffer (1 commit per tile)
        if (T + 1 < TILES) {
            const float4* src = projG4 + (T + 1) * (TK * 48);
            float4* dst = projS4 + ((T + 1) & 1) * (TK * 48);
            #pragma unroll
            for (int i = 0; i < 6; i++) CP16(dst + t + i * 256, src + t + i * 256);
        }
        asm volatile("cp.async.commit_group;" ::: "memory");

        int js = jb[w][T], je = jb[w][T + 1];
        const float* pbase = &projT[T & 1][0][0][0] + 2 * l - T * (TK * 192);
        int j = js;
        while (je - j >= 3) {              // rotation-free: regs cycle in place
            STEP3(M0, K0, j);
            STEP3(M1, K1, j + 1);
            STEP3(M2, K2, j + 2);
            j += 3;
        }
        while (j < je) {                   // exact rotating tail (<=2)
            float2 mcur = M0;  int kcur = K0;
            M0 = M1; K0 = K1; M1 = M2; K1 = K2;
            K2 = klist[w][j + 3];
            M2 = msg2[K2 * 32 + l];
            CONSUME(mcur, kcur);
            j++;
        }

        asm volatile("cp.async.wait_group 0;" ::: "memory");
        __syncthreads();
    }
#undef STEP3
#undef CONSUME
#undef CP16

    // ---- finalize: attn_out = acc * sqrt(w2) / den^2  (write into overlay) ----
    float sx = sqrtf(w2.x) / (dn.x * dn.x);
    float sy = sqrtf(w2.y) / (dn.y * dn.y);
    aoS[(w * 3 + 0) * 64 + 2 * l] = A0.x * sx;  aoS[(w * 3 + 0) * 64 + 2 * l + 1] = A0.y * sy;
    aoS[(w * 3 + 1) * 64 + 2 * l] = A1.x * sx;  aoS[(w * 3 + 1) * 64 + 2 * l + 1] = A1.y * sy;
    aoS[(w * 3 + 2) * 64 + 2 * l] = A2.x * sx;  aoS[(w * 3 + 2) * 64 + 2 * l + 1] = A2.y * sy;

    // stage Wt (transposed W_attn) into the union region
    for (int i = t; i < 4096; i += 256) {
        WtS[(i & 63) * 65 + (i >> 6)] = Wa[i];
    }
    __syncthreads();

    // ---- epilogue: out[(q,c),d] = sum_e ao[(q,c)][e] * Wa[d][e] ----
    int d = t & 63;
    int g = t >> 6;                    // 0..3 -> 6 rows each (24 rows)
    float acc[6];
    #pragma unroll
    for (int jj = 0; jj < 6; jj++) acc[jj] = 0.f;
    #pragma unroll 4
    for (int e = 0; e < 64; e++) {
        float wt = WtS[e * 65 + d];
        #pragma unroll
        for (int jj = 0; jj < 6; jj++) {
            acc[jj] = fmaf(aoS[(g + 4 * jj) * 64 + e], wt, acc[jj]);
        }
    }
    float* orow = out + ((size_t)(b * NQ + qbase) * 3) * 64;
    #pragma unroll
    for (int jj = 0; jj < 6; jj++) {
        int r = g + 4 * jj;            // r = q_local*3 + c
        orow[r * 64 + d] = acc[jj];
    }
}

extern "C" void kernel_launch(void* const* d_in, const int* in_sizes, int n_in,
                              void* d_out, int out_size) {
    const float* v_equi   = (const float*)d_in[0];
    const float* messages = (const float*)d_in[1];
    const int*   adj_mask = (const int*)d_in[2];
    const float* W_coord  = (const float*)d_in[3];
    const float* W_attn   = (const float*)d_in[4];
    float* out = (float*)d_out;

    proj_kernel<<<768, 128>>>(v_equi, W_coord);
    attn_kernel<<<BB * (NQ / 8), 256>>>(messages, adj_mask, W_attn, out);
}